// round 1
// baseline (speedup 1.0000x reference)
#include <cuda_runtime.h>
#include <cuda_bf16.h>
#include <math.h>

#define NN   50000
#define FIN  32
#define HIDD 64
#define EE   800000
#define GG   50
#define NI   10000
#define ET   (EE + NN)   // edges + self loops = 850000
#define HC   128         // heads*hid
#define SLOPE 0.2f

// ---------------- scratch (static device globals; no runtime alloc) ----------
__device__ float g_xl[NN * HC];      // per-layer transformed features [N,2,64]
__device__ float g_al[NN * 2];
__device__ float g_ar[NN * 2];
__device__ float g_h[NN * HIDD];     // current hidden
__device__ float g_xmax[NN * HIDD];  // JumpingKnowledge max
__device__ int   g_deg[NN];
__device__ int   g_rowptr[NN + 1];
__device__ int   g_cursor[NN];
__device__ int   g_perm[ET];

// ---------------- helpers ----------------------------------------------------
__device__ __forceinline__ int f2ord(float f) {
    int i = __float_as_int(f);
    return (i >= 0) ? i : (i ^ 0x7fffffff);
}
__device__ __forceinline__ float ord2f(int i) {
    return __int_as_float((i >= 0) ? i : (i ^ 0x7fffffff));
}

// ---------------- CSR build ---------------------------------------------------
__global__ void k_deg_init() {
    int i = blockIdx.x * blockDim.x + threadIdx.x;
    if (i < NN) g_deg[i] = 1;   // self loop contributes 1
}

__global__ void k_deg(const int* __restrict__ dst) {
    int i = blockIdx.x * blockDim.x + threadIdx.x;
    if (i < EE) atomicAdd(&g_deg[dst[i]], 1);
}

__global__ void k_scan() {
    __shared__ int sh[1024];
    __shared__ int carry_s;
    int tid = threadIdx.x;
    if (tid == 0) carry_s = 0;
    __syncthreads();
    for (int base = 0; base < NN; base += 1024) {
        int i = base + tid;
        int v = (i < NN) ? g_deg[i] : 0;
        sh[tid] = v;
        __syncthreads();
        for (int s = 1; s < 1024; s <<= 1) {
            int t = (tid >= s) ? sh[tid - s] : 0;
            __syncthreads();
            sh[tid] += t;
            __syncthreads();
        }
        int carry = carry_s;
        int excl = carry + sh[tid] - v;
        if (i < NN) { g_rowptr[i] = excl; g_cursor[i] = excl; }
        __syncthreads();
        if (tid == 0) carry_s = carry + sh[1023];
        __syncthreads();
    }
    if (tid == 0) g_rowptr[NN] = carry_s;
}

__global__ void k_scatter(const int* __restrict__ dst) {
    int i = blockIdx.x * blockDim.x + threadIdx.x;
    if (i < EE) {
        int d = dst[i];
        int p = atomicAdd(&g_cursor[d], 1);
        g_perm[p] = i;
    } else if (i < ET) {
        int d = i - EE;                // self loop: src = dst = d
        int p = atomicAdd(&g_cursor[d], 1);
        g_perm[p] = i;
    }
}

// ---------------- node transform: xl = h @ W ; al, ar -------------------------
// block = 128 threads (one node), tid = output column (head*64 + c)
__global__ void k_xl(const float* __restrict__ h_in,
                     const float* __restrict__ W,
                     const float* __restrict__ attl,
                     const float* __restrict__ attr,
                     int in_dim) {
    int n = blockIdx.x;
    int tid = threadIdx.x;
    __shared__ float hr[HIDD];
    __shared__ float rl[HC], rr[HC];
    const float* hp = h_in ? h_in : g_h;
    if (tid < in_dim) hr[tid] = hp[(long)n * in_dim + tid];
    __syncthreads();
    float acc = 0.f;
    #pragma unroll 8
    for (int c = 0; c < in_dim; c++) acc = fmaf(hr[c], W[c * HC + tid], acc);
    g_xl[(long)n * HC + tid] = acc;
    rl[tid] = acc * attl[tid];
    rr[tid] = acc * attr[tid];
    __syncthreads();
    for (int s = 32; s > 0; s >>= 1) {
        if ((tid & 63) < s) { rl[tid] += rl[tid + s]; rr[tid] += rr[tid + s]; }
        __syncthreads();
    }
    if ((tid & 63) == 0) {
        int hh = tid >> 6;
        g_al[n * 2 + hh] = rl[tid];
        g_ar[n * 2 + hh] = rr[tid];
    }
}

// ---------------- edge phase: one warp per dst node ---------------------------
__global__ void k_edge(const int* __restrict__ srcArr,
                       const float* __restrict__ eattr,
                       const float* __restrict__ eW,
                       const float* __restrict__ eb,
                       const float* __restrict__ bconv,
                       int layer0) {
    int warpId = (blockIdx.x * blockDim.x + threadIdx.x) >> 5;
    int lane = threadIdx.x & 31;
    if (warpId >= NN) return;
    int d = warpId;
    int beg = g_rowptr[d], end = g_rowptr[d + 1];

    float ew0[4], ew1[4], ebr[4];
    #pragma unroll
    for (int k = 0; k < 4; k++) {
        int ch = lane + 32 * k;
        ew0[k] = eW[ch];
        ew1[k] = eW[HC + ch];
        ebr[k] = eb[ch];
    }
    float ard0 = g_ar[2 * d], ard1 = g_ar[2 * d + 1];

    // pass 1: per-head max over incident edges (lane-parallel)
    float m0 = -1e30f, m1 = -1e30f;
    for (int j = beg + lane; j < end; j += 32) {
        int e = g_perm[j];
        int s = (e < EE) ? srcArr[e] : (e - EE);
        float a0 = g_al[2 * s], a1 = g_al[2 * s + 1];
        float e0 = a0 + ard0; e0 = (e0 > 0.f) ? e0 : SLOPE * e0;
        float e1 = a1 + ard1; e1 = (e1 > 0.f) ? e1 : SLOPE * e1;
        m0 = fmaxf(m0, e0); m1 = fmaxf(m1, e1);
    }
    #pragma unroll
    for (int o = 16; o > 0; o >>= 1) {
        m0 = fmaxf(m0, __shfl_xor_sync(0xffffffffu, m0, o));
        m1 = fmaxf(m1, __shfl_xor_sync(0xffffffffu, m1, o));
    }

    // pass 2: weighted accumulation; lane owns channels {lane, lane+32, lane+64, lane+96}
    float acc[4] = {0.f, 0.f, 0.f, 0.f};
    float den0 = 0.f, den1 = 0.f;
    for (int j = beg; j < end; j++) {
        int e = g_perm[j];
        int s = (e < EE) ? srcArr[e] : (e - EE);
        float a0 = g_al[2 * s], a1 = g_al[2 * s + 1];
        float e0 = a0 + ard0; e0 = (e0 > 0.f) ? e0 : SLOPE * e0;
        float e1 = a1 + ard1; e1 = (e1 > 0.f) ? e1 : SLOPE * e1;
        float w0 = __expf(e0 - m0), w1 = __expf(e1 - m1);
        den0 += w0; den1 += w1;
        float ea0 = 0.f, ea1 = 0.f;
        if (e < EE) {
            ea0 = 1.f / eattr[2 * e];
            ea1 = 1.f / eattr[2 * e + 1];
        }
        const float* xr = g_xl + (long)s * HC;
        #pragma unroll
        for (int k = 0; k < 4; k++) {
            float ee = fmaf(ea0, ew0[k], fmaf(ea1, ew1[k], ebr[k]));
            float w = (k < 2) ? w0 : w1;
            acc[k] = fmaf(xr[lane + 32 * k] + ee, w, acc[k]);
        }
    }
    den0 += 1e-16f; den1 += 1e-16f;
    float h0 = tanhf(0.5f * (acc[0] / den0 + acc[2] / den1) + bconv[lane]);
    float h1 = tanhf(0.5f * (acc[1] / den0 + acc[3] / den1) + bconv[lane + 32]);
    long o0 = (long)d * HIDD + lane;
    g_h[o0] = h0; g_h[o0 + 32] = h1;
    if (layer0) {
        g_xmax[o0] = h0; g_xmax[o0 + 32] = h1;
    } else {
        g_xmax[o0] = fmaxf(g_xmax[o0], h0);
        g_xmax[o0 + 32] = fmaxf(g_xmax[o0 + 32], h1);
    }
}

// ---------------- pooling + MLP: one block (128 thr) per graph ----------------
__global__ void k_pool(const int* __restrict__ ip,
                       const int* __restrict__ batch,
                       const float* __restrict__ gw, const float* __restrict__ gb,
                       const float* __restrict__ l1w, const float* __restrict__ l1b,
                       const float* __restrict__ l2w, const float* __restrict__ l2b,
                       float* __restrict__ out) {
    int g = blockIdx.x;
    int tid = threadIdx.x;     // 128 threads
    int lane = tid & 31, w = tid >> 5;
    __shared__ int   list[NI];
    __shared__ int   cnt;
    __shared__ float addv[HIDD], attp[HIDD];
    __shared__ int   mxv[HIDD];
    __shared__ int   gmax_i;
    __shared__ float den_sh;
    __shared__ float pooled[4 * HIDD];
    __shared__ float zsh[HC];

    if (tid == 0) { cnt = 0; gmax_i = f2ord(-1e30f); den_sh = 0.f; }
    if (tid < HIDD) { addv[tid] = 0.f; attp[tid] = 0.f; mxv[tid] = f2ord(-1e30f); }
    __syncthreads();

    // membership list
    for (int i = tid; i < NI; i += 128) {
        int node = ip[i];
        if (batch[node] == g) {
            int p = atomicAdd(&cnt, 1);
            list[p] = node;
        }
    }
    __syncthreads();
    int m = cnt;

    // pass 1: add, max, gate max
    for (int i = w; i < m; i += 4) {
        int node = list[i];
        const float* xr = g_xmax + (long)node * HIDD;
        float x0 = xr[lane], x1 = xr[lane + 32];
        float gp = x0 * gw[lane] + x1 * gw[lane + 32];
        #pragma unroll
        for (int o = 16; o > 0; o >>= 1) gp += __shfl_xor_sync(0xffffffffu, gp, o);
        atomicAdd(&addv[lane], x0);
        atomicAdd(&addv[lane + 32], x1);
        atomicMax(&mxv[lane], f2ord(x0));
        atomicMax(&mxv[lane + 32], f2ord(x1));
        if (lane == 0) atomicMax(&gmax_i, f2ord(gp + gb[0]));
    }
    __syncthreads();
    float gmax = ord2f(gmax_i);

    // pass 2: softmax-weighted attention pooling
    for (int i = w; i < m; i += 4) {
        int node = list[i];
        const float* xr = g_xmax + (long)node * HIDD;
        float x0 = xr[lane], x1 = xr[lane + 32];
        float gp = x0 * gw[lane] + x1 * gw[lane + 32];
        #pragma unroll
        for (int o = 16; o > 0; o >>= 1) gp += __shfl_xor_sync(0xffffffffu, gp, o);
        float wgt = __expf(gp + gb[0] - gmax);
        if (lane == 0) atomicAdd(&den_sh, wgt);
        atomicAdd(&attp[lane], wgt * x0);
        atomicAdd(&attp[lane + 32], wgt * x1);
    }
    __syncthreads();

    float fcnt = fmaxf((float)m, 1.f);
    if (tid < HIDD) {
        float a = addv[tid];
        pooled[tid]            = a;
        pooled[HIDD + tid]     = a / fcnt;
        pooled[2 * HIDD + tid] = attp[tid] / (den_sh + 1e-16f);
        pooled[3 * HIDD + tid] = ord2f(mxv[tid]);
    }
    __syncthreads();

    // lin1 (256x128) + tanh, then fold lin2 weight
    float acc = l1b[tid];
    #pragma unroll 8
    for (int k = 0; k < 4 * HIDD; k++) acc = fmaf(pooled[k], l1w[k * HC + tid], acc);
    zsh[tid] = tanhf(acc) * l2w[tid];
    __syncthreads();
    for (int s = 64; s > 0; s >>= 1) {
        if (tid < s) zsh[tid] += zsh[tid + s];
        __syncthreads();
    }
    if (tid == 0) out[g] = zsh[0] + l2b[0];
}

// ---------------- launch ------------------------------------------------------
extern "C" void kernel_launch(void* const* d_in, const int* in_sizes, int n_in,
                              void* d_out, int out_size) {
    // input order per setup_inputs(); graph_num may or may not be materialized
    int s = (n_in >= 21) ? 1 : 0;
    const float* x      = (const float*)d_in[0];
    const int*   eidx   = (const int*)  d_in[1];   // [2,E]
    const float* eattr  = (const float*)d_in[2];   // [E,2]
    const int*   batch  = (const int*)  d_in[3];
    const int*   ip     = (const int*)  d_in[4];
    const float* W0     = (const float*)d_in[4 + s + 1];
    const float* attl0  = (const float*)d_in[4 + s + 2];
    const float* attr0  = (const float*)d_in[4 + s + 3];
    const float* W12    = (const float*)d_in[4 + s + 4];
    const float* attl12 = (const float*)d_in[4 + s + 5];
    const float* attr12 = (const float*)d_in[4 + s + 6];
    const float* eW     = (const float*)d_in[4 + s + 7];   // [3,2,128]
    const float* eb     = (const float*)d_in[4 + s + 8];   // [3,128]
    const float* bconv  = (const float*)d_in[4 + s + 9];   // [3,64]
    const float* gw     = (const float*)d_in[4 + s + 10];
    const float* gb     = (const float*)d_in[4 + s + 11];
    const float* l1w    = (const float*)d_in[4 + s + 12];
    const float* l1b    = (const float*)d_in[4 + s + 13];
    const float* l2w    = (const float*)d_in[4 + s + 14];
    const float* l2b    = (const float*)d_in[4 + s + 15];

    const int* srcArr = eidx;
    const int* dstArr = eidx + EE;

    // CSR build (recomputed every call: deterministic, capture-safe)
    k_deg_init<<<(NN + 255) / 256, 256>>>();
    k_deg<<<(EE + 255) / 256, 256>>>(dstArr);
    k_scan<<<1, 1024>>>();
    k_scatter<<<(ET + 255) / 256, 256>>>(dstArr);

    // layer 0 (input x, F_IN=32)
    k_xl<<<NN, HC>>>(x, W0, attl0, attr0, FIN);
    k_edge<<<(NN * 32 + 255) / 256, 256>>>(srcArr, eattr, eW, eb, bconv, 1);

    // layers 1, 2 (input g_h, HID=64)
    for (int l = 0; l < 2; l++) {
        k_xl<<<NN, HC>>>(nullptr, W12 + (long)l * HIDD * HC,
                         attl12 + l * HC, attr12 + l * HC, HIDD);
        k_edge<<<(NN * 32 + 255) / 256, 256>>>(srcArr, eattr,
                                               eW + (l + 1) * 2 * HC,
                                               eb + (l + 1) * HC,
                                               bconv + (l + 1) * HIDD, 0);
    }

    k_pool<<<GG, HC>>>(ip, batch, gw, gb, l1w, l1b, l2w, l2b, (float*)d_out);
}

// round 2
// speedup vs baseline: 2.0394x; 2.0394x over previous
#include <cuda_runtime.h>
#include <cuda_bf16.h>
#include <math.h>

#define NN   50000
#define FIN  32
#define HIDD 64
#define EE   800000
#define GG   50
#define NI   10000
#define ET   (EE + NN)
#define HC   128
#define NB   ((NN + 255) / 256)   // 196 scan blocks
#define SLOPE 0.2f

// ---------------- scratch ----------------------------------------------------
__device__ __align__(128) float g_xl[NN * HC];
__device__ __align__(16)  float g_al[NN * 2];
__device__ __align__(16)  float g_ar[NN * 2];
__device__ __align__(128) float g_h[NN * HIDD];
__device__ __align__(128) float g_xmax[NN * HIDD];
__device__ int   g_deg[NN];
__device__ int   g_tmp[NN];
__device__ int   g_bsum[NB];
__device__ int   g_boff[NB];
__device__ int   g_rowptr[NN + 1];
__device__ int   g_cursor[NN];
__device__ int   g_srcp[ET];
__device__ __align__(16) float g_eap[ET * 2];
__device__ float g_v4[HIDD * 4];   // per-layer (vl0,vl1,vr0,vr1) per input dim

__device__ __forceinline__ int f2ord(float f) {
    int i = __float_as_int(f);
    return (i >= 0) ? i : (i ^ 0x7fffffff);
}
__device__ __forceinline__ float ord2f(int i) {
    return __int_as_float((i >= 0) ? i : (i ^ 0x7fffffff));
}

// ---------------- CSR build ---------------------------------------------------
__global__ void k_deg_init() {
    int i = blockIdx.x * blockDim.x + threadIdx.x;
    if (i < NN) g_deg[i] = 1;
}
__global__ void k_deg(const int* __restrict__ dst) {
    int i = blockIdx.x * blockDim.x + threadIdx.x;
    if (i < EE) atomicAdd(&g_deg[dst[i]], 1);
}
__global__ void k_scan1() {
    __shared__ int sh[256];
    int t = threadIdx.x;
    int i = blockIdx.x * 256 + t;
    int v = (i < NN) ? g_deg[i] : 0;
    sh[t] = v; __syncthreads();
    #pragma unroll
    for (int s = 1; s < 256; s <<= 1) {
        int u = (t >= s) ? sh[t - s] : 0;
        __syncthreads(); sh[t] += u; __syncthreads();
    }
    if (i < NN) g_tmp[i] = sh[t] - v;
    if (t == 255) g_bsum[blockIdx.x] = sh[255];
}
__global__ void k_scan2() {
    __shared__ int sh[256];
    int t = threadIdx.x;
    int v = (t < NB) ? g_bsum[t] : 0;
    sh[t] = v; __syncthreads();
    #pragma unroll
    for (int s = 1; s < 256; s <<= 1) {
        int u = (t >= s) ? sh[t - s] : 0;
        __syncthreads(); sh[t] += u; __syncthreads();
    }
    if (t < NB) g_boff[t] = sh[t] - v;
}
__global__ void k_scan3() {
    int i = blockIdx.x * blockDim.x + threadIdx.x;
    if (i < NN) {
        int r = g_tmp[i] + g_boff[i >> 8];
        g_rowptr[i] = r; g_cursor[i] = r;
    }
    if (i == 0) g_rowptr[NN] = ET;
}
__global__ void k_scatter(const int* __restrict__ src, const int* __restrict__ dst,
                          const float* __restrict__ eattr) {
    int i = blockIdx.x * blockDim.x + threadIdx.x;
    if (i < EE) {
        int d = dst[i];
        int p = atomicAdd(&g_cursor[d], 1);
        g_srcp[p] = src[i];
        g_eap[2 * p]     = 1.0f / eattr[2 * i];
        g_eap[2 * p + 1] = 1.0f / eattr[2 * i + 1];
    } else if (i < ET) {
        int d = i - EE;
        int p = atomicAdd(&g_cursor[d], 1);
        g_srcp[p] = d;
        g_eap[2 * p] = 0.f; g_eap[2 * p + 1] = 0.f;
    }
}

// ---------------- v = W @ att (per layer, tiny) -------------------------------
__global__ void k_prep(const float* __restrict__ W,
                       const float* __restrict__ attl,
                       const float* __restrict__ attr, int in_dim) {
    int t = threadIdx.x;                 // t = in*2 + h
    if (t >= in_dim * 2) return;
    int in = t >> 1, h = t & 1;
    float vl = 0.f, vr = 0.f;
    const float* wr = W + in * HC + h * HIDD;
    const float* alp = attl + h * HIDD;
    const float* arp = attr + h * HIDD;
    #pragma unroll 8
    for (int c = 0; c < HIDD; c++) {
        vl = fmaf(wr[c], alp[c], vl);
        vr = fmaf(wr[c], arp[c], vr);
    }
    g_v4[in * 4 + h]     = vl;
    g_v4[in * 4 + 2 + h] = vr;
}

// ---------------- node transform (tiled, W cached in smem) --------------------
// block = 128 threads; processes 4 nodes per iteration, grid-stride.
__global__ __launch_bounds__(128) void k_xl(const float* __restrict__ h_in,
                                            const float* __restrict__ W, int in_dim) {
    extern __shared__ float smem[];
    float* Wsh = smem;                    // in_dim * 128
    float* vsh = Wsh + in_dim * HC;       // in_dim * 4
    float* hr  = vsh + in_dim * 4;        // 4 * in_dim
    int tid = threadIdx.x;
    const float* hp = h_in ? h_in : g_h;

    for (int i = tid; i < in_dim * HC; i += 128) Wsh[i] = W[i];
    for (int i = tid; i < in_dim * 4; i += 128) vsh[i] = g_v4[i];
    __syncthreads();

    for (int n0 = blockIdx.x * 4; n0 < NN; n0 += gridDim.x * 4) {
        int cnt = min(4, NN - n0);
        int tot = cnt * in_dim;
        for (int i = tid; i < tot; i += 128) hr[i] = hp[(long)n0 * in_dim + i];
        __syncthreads();

        float a0 = 0.f, a1 = 0.f, a2 = 0.f, a3 = 0.f;
        for (int c = 0; c < in_dim; c++) {
            float w = Wsh[c * HC + tid];
            a0 = fmaf(hr[c], w, a0);
            a1 = fmaf(hr[in_dim + c], w, a1);
            a2 = fmaf(hr[2 * in_dim + c], w, a2);
            a3 = fmaf(hr[3 * in_dim + c], w, a3);
        }
        g_xl[(long)n0 * HC + tid] = a0;
        if (cnt > 1) g_xl[(long)(n0 + 1) * HC + tid] = a1;
        if (cnt > 2) g_xl[(long)(n0 + 2) * HC + tid] = a2;
        if (cnt > 3) g_xl[(long)(n0 + 3) * HC + tid] = a3;

        if (tid < 4 * cnt * 0 + 16) {        // 16 threads: i = node, q = quantity
            int i = tid >> 2, q = tid & 3;
            if (i < cnt) {
                float v = 0.f;
                #pragma unroll 8
                for (int c = 0; c < in_dim; c++)
                    v = fmaf(hr[i * in_dim + c], vsh[c * 4 + q], v);
                int n = n0 + i;
                if (q < 2) g_al[n * 2 + q] = v;
                else       g_ar[n * 2 + (q - 2)] = v;
            }
        }
        __syncthreads();
    }
}

// ---------------- edge phase: one warp per dst, factored message sum ----------
__global__ __launch_bounds__(256) void k_edge(const float* __restrict__ eW,
                                              const float* __restrict__ eb,
                                              const float* __restrict__ bconv,
                                              int layer0) {
    int warpId = (blockIdx.x * blockDim.x + threadIdx.x) >> 5;
    int lane = threadIdx.x & 31;
    if (warpId >= NN) return;
    int d = warpId;
    int beg = g_rowptr[d], end = g_rowptr[d + 1];
    int head = lane >> 4;

    const float2* al2 = (const float2*)g_al;
    const float2* ea2 = (const float2*)g_eap;
    float2 arv = ((const float2*)g_ar)[d];
    float ard = head ? arv.y : arv.x;

    float4 acc = {0.f, 0.f, 0.f, 0.f};
    float S0 = 0.f, S1 = 0.f, den = 0.f;

    for (int j = beg; j < end; j++) {
        int s = g_srcp[j];
        float2 a = al2[s];
        float2 ea = ea2[j];
        float al = head ? a.y : a.x;
        float e = al + ard;
        e = (e > 0.f) ? e : SLOPE * e;
        e = fminf(e, 80.f);
        float w = __expf(e);
        den += w; S0 = fmaf(w, ea.x, S0); S1 = fmaf(w, ea.y, S1);
        float4 xv = ((const float4*)(g_xl + (long)s * HC))[lane];
        acc.x = fmaf(w, xv.x, acc.x);
        acc.y = fmaf(w, xv.y, acc.y);
        acc.z = fmaf(w, xv.z, acc.z);
        acc.w = fmaf(w, xv.w, acc.w);
    }

    float4 ew0 = ((const float4*)eW)[lane];
    float4 ew1 = ((const float4*)(eW + HC))[lane];
    float4 ebv = ((const float4*)eb)[lane];
    float inv = 1.f / (den + 1e-16f);
    float v0 = (acc.x + ew0.x * S0 + ew1.x * S1 + ebv.x * den) * inv;
    float v1 = (acc.y + ew0.y * S0 + ew1.y * S1 + ebv.y * den) * inv;
    float v2 = (acc.z + ew0.z * S0 + ew1.z * S1 + ebv.z * den) * inv;
    float v3 = (acc.w + ew0.w * S0 + ew1.w * S1 + ebv.w * den) * inv;

    // combine heads: lane l (<16) has head0 channels 4l..4l+3, lane l+16 head1
    float p0 = __shfl_xor_sync(0xffffffffu, v0, 16);
    float p1 = __shfl_xor_sync(0xffffffffu, v1, 16);
    float p2 = __shfl_xor_sync(0xffffffffu, v2, 16);
    float p3 = __shfl_xor_sync(0xffffffffu, v3, 16);

    if (lane < 16) {
        float4 bc = ((const float4*)bconv)[lane];
        float4 hv;
        hv.x = tanhf(0.5f * (v0 + p0) + bc.x);
        hv.y = tanhf(0.5f * (v1 + p1) + bc.y);
        hv.z = tanhf(0.5f * (v2 + p2) + bc.z);
        hv.w = tanhf(0.5f * (v3 + p3) + bc.w);
        float4* hp = (float4*)(g_h + (long)d * HIDD);
        float4* xp = (float4*)(g_xmax + (long)d * HIDD);
        hp[lane] = hv;
        if (layer0) {
            xp[lane] = hv;
        } else {
            float4 xo = xp[lane];
            xo.x = fmaxf(xo.x, hv.x); xo.y = fmaxf(xo.y, hv.y);
            xo.z = fmaxf(xo.z, hv.z); xo.w = fmaxf(xo.w, hv.w);
            xp[lane] = xo;
        }
    }
}

// ---------------- pooling + MLP ----------------------------------------------
__global__ void k_pool(const int* __restrict__ ip,
                       const int* __restrict__ batch,
                       const float* __restrict__ gw, const float* __restrict__ gb,
                       const float* __restrict__ l1w, const float* __restrict__ l1b,
                       const float* __restrict__ l2w, const float* __restrict__ l2b,
                       float* __restrict__ out) {
    int g = blockIdx.x;
    int tid = threadIdx.x;
    int lane = tid & 31, w = tid >> 5;
    __shared__ int   list[NI];
    __shared__ int   cnt;
    __shared__ float addv[HIDD], attp[HIDD];
    __shared__ int   mxv[HIDD];
    __shared__ int   gmax_i;
    __shared__ float den_sh;
    __shared__ float pooled[4 * HIDD];
    __shared__ float zsh[HC];

    if (tid == 0) { cnt = 0; gmax_i = f2ord(-1e30f); den_sh = 0.f; }
    if (tid < HIDD) { addv[tid] = 0.f; attp[tid] = 0.f; mxv[tid] = f2ord(-1e30f); }
    __syncthreads();

    for (int i = tid; i < NI; i += 128) {
        int node = ip[i];
        if (batch[node] == g) {
            int p = atomicAdd(&cnt, 1);
            list[p] = node;
        }
    }
    __syncthreads();
    int m = cnt;

    for (int i = w; i < m; i += 4) {
        int node = list[i];
        const float* xr = g_xmax + (long)node * HIDD;
        float x0 = xr[lane], x1 = xr[lane + 32];
        float gp = x0 * gw[lane] + x1 * gw[lane + 32];
        #pragma unroll
        for (int o = 16; o > 0; o >>= 1) gp += __shfl_xor_sync(0xffffffffu, gp, o);
        atomicAdd(&addv[lane], x0);
        atomicAdd(&addv[lane + 32], x1);
        atomicMax(&mxv[lane], f2ord(x0));
        atomicMax(&mxv[lane + 32], f2ord(x1));
        if (lane == 0) atomicMax(&gmax_i, f2ord(gp + gb[0]));
    }
    __syncthreads();
    float gmax = ord2f(gmax_i);

    for (int i = w; i < m; i += 4) {
        int node = list[i];
        const float* xr = g_xmax + (long)node * HIDD;
        float x0 = xr[lane], x1 = xr[lane + 32];
        float gp = x0 * gw[lane] + x1 * gw[lane + 32];
        #pragma unroll
        for (int o = 16; o > 0; o >>= 1) gp += __shfl_xor_sync(0xffffffffu, gp, o);
        float wgt = __expf(gp + gb[0] - gmax);
        if (lane == 0) atomicAdd(&den_sh, wgt);
        atomicAdd(&attp[lane], wgt * x0);
        atomicAdd(&attp[lane + 32], wgt * x1);
    }
    __syncthreads();

    float fcnt = fmaxf((float)m, 1.f);
    if (tid < HIDD) {
        float a = addv[tid];
        pooled[tid]            = a;
        pooled[HIDD + tid]     = a / fcnt;
        pooled[2 * HIDD + tid] = attp[tid] / (den_sh + 1e-16f);
        pooled[3 * HIDD + tid] = ord2f(mxv[tid]);
    }
    __syncthreads();

    float acc = l1b[tid];
    #pragma unroll 8
    for (int k = 0; k < 4 * HIDD; k++) acc = fmaf(pooled[k], l1w[k * HC + tid], acc);
    zsh[tid] = tanhf(acc) * l2w[tid];
    __syncthreads();
    for (int s = 64; s > 0; s >>= 1) {
        if (tid < s) zsh[tid] += zsh[tid + s];
        __syncthreads();
    }
    if (tid == 0) out[g] = zsh[0] + l2b[0];
}

// ---------------- launch ------------------------------------------------------
extern "C" void kernel_launch(void* const* d_in, const int* in_sizes, int n_in,
                              void* d_out, int out_size) {
    int s = (n_in >= 21) ? 1 : 0;
    const float* x      = (const float*)d_in[0];
    const int*   eidx   = (const int*)  d_in[1];
    const float* eattr  = (const float*)d_in[2];
    const int*   batch  = (const int*)  d_in[3];
    const int*   ip     = (const int*)  d_in[4];
    const float* W0     = (const float*)d_in[4 + s + 1];
    const float* attl0  = (const float*)d_in[4 + s + 2];
    const float* attr0  = (const float*)d_in[4 + s + 3];
    const float* W12    = (const float*)d_in[4 + s + 4];
    const float* attl12 = (const float*)d_in[4 + s + 5];
    const float* attr12 = (const float*)d_in[4 + s + 6];
    const float* eW     = (const float*)d_in[4 + s + 7];
    const float* eb     = (const float*)d_in[4 + s + 8];
    const float* bconv  = (const float*)d_in[4 + s + 9];
    const float* gw     = (const float*)d_in[4 + s + 10];
    const float* gb     = (const float*)d_in[4 + s + 11];
    const float* l1w    = (const float*)d_in[4 + s + 12];
    const float* l1b    = (const float*)d_in[4 + s + 13];
    const float* l2w    = (const float*)d_in[4 + s + 14];
    const float* l2b    = (const float*)d_in[4 + s + 15];

    const int* srcArr = eidx;
    const int* dstArr = eidx + EE;

    // CSR build
    k_deg_init<<<(NN + 255) / 256, 256>>>();
    k_deg<<<(EE + 255) / 256, 256>>>(dstArr);
    k_scan1<<<NB, 256>>>();
    k_scan2<<<1, 256>>>();
    k_scan3<<<NB, 256>>>();
    k_scatter<<<(ET + 255) / 256, 256>>>(srcArr, dstArr, eattr);

    int xl_smem32 = (FIN  * HC + FIN  * 4 + 4 * FIN)  * sizeof(float);
    int xl_smem64 = (HIDD * HC + HIDD * 4 + 4 * HIDD) * sizeof(float);

    // layer 0
    k_prep<<<1, 128>>>(W0, attl0, attr0, FIN);
    k_xl<<<888, 128, xl_smem32>>>(x, W0, FIN);
    k_edge<<<(NN * 32 + 255) / 256, 256>>>(eW, eb, bconv, 1);

    // layers 1,2
    for (int l = 0; l < 2; l++) {
        const float* Wl = W12 + (long)l * HIDD * HC;
        k_prep<<<1, 128>>>(Wl, attl12 + l * HC, attr12 + l * HC, HIDD);
        k_xl<<<888, 128, xl_smem64>>>(nullptr, Wl, HIDD);
        k_edge<<<(NN * 32 + 255) / 256, 256>>>(eW + (l + 1) * 2 * HC,
                                               eb + (l + 1) * HC,
                                               bconv + (l + 1) * HIDD, 0);
    }

    k_pool<<<GG, HC>>>(ip, batch, gw, gb, l1w, l1b, l2w, l2b, (float*)d_out);
}

// round 3
// speedup vs baseline: 2.3209x; 1.1380x over previous
#include <cuda_runtime.h>
#include <cuda_fp16.h>
#include <math.h>

#define NN   50000
#define FIN  32
#define HIDD 64
#define EE   800000
#define GG   50
#define NI   10000
#define ET   (EE + NN)
#define HC   128
#define NB   ((NN + 255) / 256)
#define SLOPE 0.2f

typedef unsigned long long ull;

// ---------------- scratch ----------------------------------------------------
__device__ __align__(256) __half g_xlh[NN * HC];      // fp16 transformed feats
__device__ __align__(16)  float g_al[NN * 2];
__device__ __align__(16)  float g_ar[NN * 2];
__device__ __align__(256) float g_h[NN * HIDD];
__device__ __align__(256) float g_xmax[NN * HIDD];
__device__ int    g_deg[NN];
__device__ int    g_tmp[NN];
__device__ int    g_bsum[NB];
__device__ int    g_boff[NB];
__device__ int    g_rowptr[NN + 1];
__device__ int    g_cursor[NN];
__device__ __align__(16) float4 g_pack[ET];           // {srcBits, 1/ea0, 1/ea1, 0}
__device__ float  g_v4[3 * HIDD * 4];                 // per-layer att projections

__device__ __forceinline__ int f2ord(float f) {
    int i = __float_as_int(f);
    return (i >= 0) ? i : (i ^ 0x7fffffff);
}
__device__ __forceinline__ float ord2f(int i) {
    return __int_as_float((i >= 0) ? i : (i ^ 0x7fffffff));
}
__device__ __forceinline__ ull ffma2(ull a, ull b, ull c) {
    ull d;
    asm("fma.rn.f32x2 %0, %1, %2, %3;" : "=l"(d) : "l"(a), "l"(b), "l"(c));
    return d;
}
__device__ __forceinline__ ull dup2(float v) {
    unsigned int vi = __float_as_uint(v);
    ull u;
    asm("mov.b64 %0, {%1, %1};" : "=l"(u) : "r"(vi));
    return u;
}

// ---------------- CSR build ---------------------------------------------------
__global__ void k_deg_init() {
    int i = blockIdx.x * blockDim.x + threadIdx.x;
    if (i < NN) g_deg[i] = 1;
}
__global__ void k_deg(const int* __restrict__ dst) {
    int i = blockIdx.x * blockDim.x + threadIdx.x;
    if (i < EE) atomicAdd(&g_deg[dst[i]], 1);
}
__global__ void k_scan1() {
    __shared__ int sh[256];
    int t = threadIdx.x;
    int i = blockIdx.x * 256 + t;
    int v = (i < NN) ? g_deg[i] : 0;
    sh[t] = v; __syncthreads();
    #pragma unroll
    for (int s = 1; s < 256; s <<= 1) {
        int u = (t >= s) ? sh[t - s] : 0;
        __syncthreads(); sh[t] += u; __syncthreads();
    }
    if (i < NN) g_tmp[i] = sh[t] - v;
    if (t == 255) g_bsum[blockIdx.x] = sh[255];
}
__global__ void k_scan2() {
    __shared__ int sh[256];
    int t = threadIdx.x;
    int v = (t < NB) ? g_bsum[t] : 0;
    sh[t] = v; __syncthreads();
    #pragma unroll
    for (int s = 1; s < 256; s <<= 1) {
        int u = (t >= s) ? sh[t - s] : 0;
        __syncthreads(); sh[t] += u; __syncthreads();
    }
    if (t < NB) g_boff[t] = sh[t] - v;
}
__global__ void k_scan3() {
    int i = blockIdx.x * blockDim.x + threadIdx.x;
    if (i < NN) {
        int r = g_tmp[i] + g_boff[i >> 8];
        g_rowptr[i] = r; g_cursor[i] = r;
    }
    if (i == 0) g_rowptr[NN] = ET;
}
__global__ void k_scatter(const int* __restrict__ src, const int* __restrict__ dst,
                          const float* __restrict__ eattr) {
    int i = blockIdx.x * blockDim.x + threadIdx.x;
    if (i < EE) {
        int d = dst[i];
        int p = atomicAdd(&g_cursor[d], 1);
        g_pack[p] = make_float4(__int_as_float(src[i]),
                                1.0f / eattr[2 * i], 1.0f / eattr[2 * i + 1], 0.f);
    } else if (i < ET) {
        int d = i - EE;
        int p = atomicAdd(&g_cursor[d], 1);
        g_pack[p] = make_float4(__int_as_float(d), 0.f, 0.f, 0.f);
    }
}

// ---------------- all 3 layers' attention projections: v = W @ att -----------
__global__ void k_prep_all(const float* __restrict__ W0,
                           const float* __restrict__ attl0,
                           const float* __restrict__ attr0,
                           const float* __restrict__ W12,
                           const float* __restrict__ attl12,
                           const float* __restrict__ attr12) {
    int l = blockIdx.x;
    const float* W;
    const float* attl;
    const float* attr;
    int in_dim;
    if (l == 0) { W = W0; attl = attl0; attr = attr0; in_dim = FIN; }
    else {
        W = W12 + (long)(l - 1) * HIDD * HC;
        attl = attl12 + (l - 1) * HC;
        attr = attr12 + (l - 1) * HC;
        in_dim = HIDD;
    }
    int t = threadIdx.x;
    if (t >= in_dim * 2) return;
    int in = t >> 1, h = t & 1;
    float vl = 0.f, vr = 0.f;
    const float* wr = W + in * HC + h * HIDD;
    const float* alp = attl + h * HIDD;
    const float* arp = attr + h * HIDD;
    #pragma unroll 8
    for (int c = 0; c < HIDD; c++) {
        vl = fmaf(wr[c], alp[c], vl);
        vr = fmaf(wr[c], arp[c], vr);
    }
    g_v4[l * 256 + in * 4 + h]     = vl;
    g_v4[l * 256 + in * 4 + 2 + h] = vr;
}

// ---------------- node transform: f32x2 FFMA, fp16 output ---------------------
// block 128; 8 nodes per tile; thread: col pair (tid&63), node group (tid>>6)*4.
__global__ __launch_bounds__(128) void k_xl(const float* __restrict__ h_in,
                                            const float* __restrict__ W,
                                            int in_dim, int layer) {
    extern __shared__ char smraw[];
    ull*   Wsh = (ull*)smraw;                  // in_dim * 64
    ull*   hr2 = Wsh + in_dim * 64;            // 8 * in_dim (dup-packed)
    float* vsh = (float*)(hr2 + 8 * in_dim);   // in_dim * 4
    int tid = threadIdx.x;
    const float* hp = h_in ? h_in : g_h;

    for (int i = tid; i < in_dim * 64; i += 128)
        Wsh[i] = reinterpret_cast<const ull*>(W)[i];
    for (int i = tid; i < in_dim * 4; i += 128)
        vsh[i] = g_v4[layer * 256 + i];
    __syncthreads();

    int c2 = tid & 63, ng = tid >> 6;

    for (int n0 = blockIdx.x * 8; n0 < NN; n0 += gridDim.x * 8) {
        for (int i = tid; i < 8 * in_dim; i += 128)
            hr2[i] = dup2(hp[(long)n0 * in_dim + i]);
        __syncthreads();

        ull acc[4] = {0ull, 0ull, 0ull, 0ull};
        const ull* hb = hr2 + ng * 4 * in_dim;
        #pragma unroll 8
        for (int c = 0; c < in_dim; c++) {
            ull w = Wsh[c * 64 + c2];
            acc[0] = ffma2(hb[c], w, acc[0]);
            acc[1] = ffma2(hb[in_dim + c], w, acc[1]);
            acc[2] = ffma2(hb[2 * in_dim + c], w, acc[2]);
            acc[3] = ffma2(hb[3 * in_dim + c], w, acc[3]);
        }
        #pragma unroll
        for (int k = 0; k < 4; k++) {
            int n = n0 + ng * 4 + k;
            float lo = __uint_as_float((unsigned)acc[k]);
            float hi = __uint_as_float((unsigned)(acc[k] >> 32));
            *((__half2*)(g_xlh + (long)n * HC) + c2) = __floats2half2_rn(lo, hi);
        }

        if (tid < 32) {               // 8 nodes x 4 quantities
            int i = tid >> 2, q = tid & 3;
            float v = 0.f;
            #pragma unroll 8
            for (int c = 0; c < in_dim; c++)
                v = fmaf(__uint_as_float((unsigned)hr2[i * in_dim + c]),
                         vsh[c * 4 + q], v);
            int n = n0 + i;
            if (q < 2) g_al[n * 2 + q] = v;
            else       g_ar[n * 2 + (q - 2)] = v;
        }
        __syncthreads();
    }
}

// ---------------- edge phase: one warp per dst, fp16 gather -------------------
__global__ __launch_bounds__(256) void k_edge(const float* __restrict__ eW,
                                              const float* __restrict__ eb,
                                              const float* __restrict__ bconv,
                                              int layer0) {
    int warpId = (blockIdx.x * blockDim.x + threadIdx.x) >> 5;
    int lane = threadIdx.x & 31;
    if (warpId >= NN) return;
    int d = warpId;
    int beg = g_rowptr[d], end = g_rowptr[d + 1];
    int head = lane >> 4;

    const float2* al2 = (const float2*)g_al;
    float2 arv = ((const float2*)g_ar)[d];
    float ard = head ? arv.y : arv.x;

    float a0 = 0.f, a1 = 0.f, a2 = 0.f, a3 = 0.f;
    float S0 = 0.f, S1 = 0.f, den = 0.f;

    #pragma unroll 2
    for (int j = beg; j < end; j++) {
        float4 p = g_pack[j];
        int s = __float_as_int(p.x);
        float2 a = al2[s];
        float al = head ? a.y : a.x;
        float e = al + ard;
        e = (e > 0.f) ? e : SLOPE * e;
        e = fminf(e, 80.f);
        float w = __expf(e);
        den += w;
        S0 = fmaf(w, p.y, S0);
        S1 = fmaf(w, p.z, S1);
        uint2 v = *((const uint2*)(g_xlh + (long)s * HC) + lane);
        float2 f01 = __half22float2(*reinterpret_cast<__half2*>(&v.x));
        float2 f23 = __half22float2(*reinterpret_cast<__half2*>(&v.y));
        a0 = fmaf(w, f01.x, a0);
        a1 = fmaf(w, f01.y, a1);
        a2 = fmaf(w, f23.x, a2);
        a3 = fmaf(w, f23.y, a3);
    }

    float4 ew0 = ((const float4*)eW)[lane];
    float4 ew1 = ((const float4*)(eW + HC))[lane];
    float4 ebv = ((const float4*)eb)[lane];
    float inv = 1.f / (den + 1e-16f);
    float v0 = (a0 + ew0.x * S0 + ew1.x * S1 + ebv.x * den) * inv;
    float v1 = (a1 + ew0.y * S0 + ew1.y * S1 + ebv.y * den) * inv;
    float v2 = (a2 + ew0.z * S0 + ew1.z * S1 + ebv.z * den) * inv;
    float v3 = (a3 + ew0.w * S0 + ew1.w * S1 + ebv.w * den) * inv;

    float p0 = __shfl_xor_sync(0xffffffffu, v0, 16);
    float p1 = __shfl_xor_sync(0xffffffffu, v1, 16);
    float p2 = __shfl_xor_sync(0xffffffffu, v2, 16);
    float p3 = __shfl_xor_sync(0xffffffffu, v3, 16);

    if (lane < 16) {
        float4 bc = ((const float4*)bconv)[lane];
        float4 hv;
        hv.x = tanhf(0.5f * (v0 + p0) + bc.x);
        hv.y = tanhf(0.5f * (v1 + p1) + bc.y);
        hv.z = tanhf(0.5f * (v2 + p2) + bc.z);
        hv.w = tanhf(0.5f * (v3 + p3) + bc.w);
        float4* hp = (float4*)(g_h + (long)d * HIDD);
        float4* xp = (float4*)(g_xmax + (long)d * HIDD);
        hp[lane] = hv;
        if (layer0) {
            xp[lane] = hv;
        } else {
            float4 xo = xp[lane];
            xo.x = fmaxf(xo.x, hv.x); xo.y = fmaxf(xo.y, hv.y);
            xo.z = fmaxf(xo.z, hv.z); xo.w = fmaxf(xo.w, hv.w);
            xp[lane] = xo;
        }
    }
}

// ---------------- pooling + MLP ----------------------------------------------
__global__ void k_pool(const int* __restrict__ ip,
                       const int* __restrict__ batch,
                       const float* __restrict__ gw, const float* __restrict__ gb,
                       const float* __restrict__ l1w, const float* __restrict__ l1b,
                       const float* __restrict__ l2w, const float* __restrict__ l2b,
                       float* __restrict__ out) {
    int g = blockIdx.x;
    int tid = threadIdx.x;
    int lane = tid & 31, w = tid >> 5;
    __shared__ int   list[NI];
    __shared__ int   cnt;
    __shared__ float addv[HIDD], attp[HIDD];
    __shared__ int   mxv[HIDD];
    __shared__ int   gmax_i;
    __shared__ float den_sh;
    __shared__ float pooled[4 * HIDD];
    __shared__ float zsh[HC];

    if (tid == 0) { cnt = 0; gmax_i = f2ord(-1e30f); den_sh = 0.f; }
    if (tid < HIDD) { addv[tid] = 0.f; attp[tid] = 0.f; mxv[tid] = f2ord(-1e30f); }
    __syncthreads();

    for (int i = tid; i < NI; i += 128) {
        int node = ip[i];
        if (batch[node] == g) {
            int p = atomicAdd(&cnt, 1);
            list[p] = node;
        }
    }
    __syncthreads();
    int m = cnt;

    for (int i = w; i < m; i += 4) {
        int node = list[i];
        const float* xr = g_xmax + (long)node * HIDD;
        float x0 = xr[lane], x1 = xr[lane + 32];
        float gp = x0 * gw[lane] + x1 * gw[lane + 32];
        #pragma unroll
        for (int o = 16; o > 0; o >>= 1) gp += __shfl_xor_sync(0xffffffffu, gp, o);
        atomicAdd(&addv[lane], x0);
        atomicAdd(&addv[lane + 32], x1);
        atomicMax(&mxv[lane], f2ord(x0));
        atomicMax(&mxv[lane + 32], f2ord(x1));
        if (lane == 0) atomicMax(&gmax_i, f2ord(gp + gb[0]));
    }
    __syncthreads();
    float gmax = ord2f(gmax_i);

    for (int i = w; i < m; i += 4) {
        int node = list[i];
        const float* xr = g_xmax + (long)node * HIDD;
        float x0 = xr[lane], x1 = xr[lane + 32];
        float gp = x0 * gw[lane] + x1 * gw[lane + 32];
        #pragma unroll
        for (int o = 16; o > 0; o >>= 1) gp += __shfl_xor_sync(0xffffffffu, gp, o);
        float wgt = __expf(gp + gb[0] - gmax);
        if (lane == 0) atomicAdd(&den_sh, wgt);
        atomicAdd(&attp[lane], wgt * x0);
        atomicAdd(&attp[lane + 32], wgt * x1);
    }
    __syncthreads();

    float fcnt = fmaxf((float)m, 1.f);
    if (tid < HIDD) {
        float a = addv[tid];
        pooled[tid]            = a;
        pooled[HIDD + tid]     = a / fcnt;
        pooled[2 * HIDD + tid] = attp[tid] / (den_sh + 1e-16f);
        pooled[3 * HIDD + tid] = ord2f(mxv[tid]);
    }
    __syncthreads();

    float acc = l1b[tid];
    #pragma unroll 8
    for (int k = 0; k < 4 * HIDD; k++) acc = fmaf(pooled[k], l1w[k * HC + tid], acc);
    zsh[tid] = tanhf(acc) * l2w[tid];
    __syncthreads();
    for (int s = 64; s > 0; s >>= 1) {
        if (tid < s) zsh[tid] += zsh[tid + s];
        __syncthreads();
    }
    if (tid == 0) out[g] = zsh[0] + l2b[0];
}

// ---------------- launch ------------------------------------------------------
extern "C" void kernel_launch(void* const* d_in, const int* in_sizes, int n_in,
                              void* d_out, int out_size) {
    int s = (n_in >= 21) ? 1 : 0;
    const float* x      = (const float*)d_in[0];
    const int*   eidx   = (const int*)  d_in[1];
    const float* eattr  = (const float*)d_in[2];
    const int*   batch  = (const int*)  d_in[3];
    const int*   ip     = (const int*)  d_in[4];
    const float* W0     = (const float*)d_in[4 + s + 1];
    const float* attl0  = (const float*)d_in[4 + s + 2];
    const float* attr0  = (const float*)d_in[4 + s + 3];
    const float* W12    = (const float*)d_in[4 + s + 4];
    const float* attl12 = (const float*)d_in[4 + s + 5];
    const float* attr12 = (const float*)d_in[4 + s + 6];
    const float* eW     = (const float*)d_in[4 + s + 7];
    const float* eb     = (const float*)d_in[4 + s + 8];
    const float* bconv  = (const float*)d_in[4 + s + 9];
    const float* gw     = (const float*)d_in[4 + s + 10];
    const float* gb     = (const float*)d_in[4 + s + 11];
    const float* l1w    = (const float*)d_in[4 + s + 12];
    const float* l1b    = (const float*)d_in[4 + s + 13];
    const float* l2w    = (const float*)d_in[4 + s + 14];
    const float* l2b    = (const float*)d_in[4 + s + 15];

    const int* srcArr = eidx;
    const int* dstArr = eidx + EE;

    // CSR build
    k_deg_init<<<(NN + 255) / 256, 256>>>();
    k_deg<<<(EE + 255) / 256, 256>>>(dstArr);
    k_scan1<<<NB, 256>>>();
    k_scan2<<<1, 256>>>();
    k_scan3<<<NB, 256>>>();
    k_scatter<<<(ET + 255) / 256, 256>>>(srcArr, dstArr, eattr);

    k_prep_all<<<3, 128>>>(W0, attl0, attr0, W12, attl12, attr12);

    int sm32 = (FIN  * 64 + 8 * FIN)  * 8 + FIN  * 4 * 4;
    int sm64 = (HIDD * 64 + 8 * HIDD) * 8 + HIDD * 4 * 4;

    // layer 0
    k_xl<<<592, 128, sm32>>>(x, W0, FIN, 0);
    k_edge<<<(NN * 32 + 255) / 256, 256>>>(eW, eb, bconv, 1);

    // layers 1,2
    for (int l = 0; l < 2; l++) {
        const float* Wl = W12 + (long)l * HIDD * HC;
        k_xl<<<592, 128, sm64>>>(nullptr, Wl, HIDD, l + 1);
        k_edge<<<(NN * 32 + 255) / 256, 256>>>(eW + (l + 1) * 2 * HC,
                                               eb + (l + 1) * HC,
                                               bconv + (l + 1) * HIDD, 0);
    }

    k_pool<<<GG, HC>>>(ip, batch, gw, gb, l1w, l1b, l2w, l2b, (float*)d_out);
}